// round 6
// baseline (speedup 1.0000x reference)
#include <cuda_runtime.h>
#include <cuda_bf16.h>
#include <cstdint>

// Problem constants
#define M_ROWS 16384      // 8 * 2048
#define D_IN   512
#define NB     8
#define KTOT   4608       // 512 (relu base) + 512*8 (bs+rbf)
#define N_OUT  512

// GEMM tiling (mma.sync path, base compute_100 features only)
#define BM 128
#define BN 128
#define BK 32                       // bf16 K per stage
#define NITER (KTOT / BK)           // 144
#define ASTRIDE 80                  // bytes per smem row: 32 bf16 (64B) + 16B pad
#define A_BYTES (BM * ASTRIDE)      // 10240
#define B_BYTES (BN * ASTRIDE)      // 10240
#define STG_BYTES (2 * A_BYTES + 2 * B_BYTES)   // 40960: Ah | Al | Bh | Bl
#define SMEM_TOTAL (2 * STG_BYTES)              // 81920

// Scratch: bf16 hi/lo split feature + weight matrices
__device__ __nv_bfloat16 g_Fh[(size_t)M_ROWS * KTOT];
__device__ __nv_bfloat16 g_Fl[(size_t)M_ROWS * KTOT];
__device__ __nv_bfloat16 g_Wh[(size_t)N_OUT * KTOT];
__device__ __nv_bfloat16 g_Wl[(size_t)N_OUT * KTOT];

// ---------------------------------------------------------------------------
// PTX helpers — all base sm_80-class features, valid on compute_100
// ---------------------------------------------------------------------------
__device__ __forceinline__ uint32_t smem_u32(const void* p) {
    uint32_t a;
    asm("{ .reg .u64 t; cvta.to.shared.u64 t, %1; cvt.u32.u64 %0, t; }" : "=r"(a) : "l"(p));
    return a;
}
__device__ __forceinline__ void cp_async16(uint32_t s, const void* g) {
    asm volatile("cp.async.cg.shared.global [%0], [%1], 16;" :: "r"(s), "l"(g));
}
#define CP_COMMIT() asm volatile("cp.async.commit_group;" ::: "memory")
#define CP_WAIT(n)  asm volatile("cp.async.wait_group %0;" :: "n"(n) : "memory")

__device__ __forceinline__ void ldsm4(uint32_t* r, uint32_t addr) {
    asm volatile("ldmatrix.sync.aligned.m8n8.x4.shared.b16 {%0,%1,%2,%3}, [%4];"
                 : "=r"(r[0]), "=r"(r[1]), "=r"(r[2]), "=r"(r[3]) : "r"(addr));
}
__device__ __forceinline__ void mma16816(float* c, const uint32_t* a,
                                         uint32_t b0, uint32_t b1) {
    asm volatile("mma.sync.aligned.m16n8k16.row.col.f32.bf16.bf16.f32 "
                 "{%0,%1,%2,%3}, {%4,%5,%6,%7}, {%8,%9}, {%0,%1,%2,%3};"
                 : "+f"(c[0]), "+f"(c[1]), "+f"(c[2]), "+f"(c[3])
                 : "r"(a[0]), "r"(a[1]), "r"(a[2]), "r"(a[3]), "r"(b0), "r"(b1));
}

// ---------------------------------------------------------------------------
// Kernel 0: split weights to bf16 hi/lo, concat [base | spline]
// ---------------------------------------------------------------------------
__global__ void prep_kernel(const float* __restrict__ bw,
                            const float* __restrict__ sw) {
    int o = blockIdx.x;           // 0..511
    int t = threadIdx.x;          // 256 threads
    size_t rb = (size_t)o * KTOT;
    for (int k = t; k < D_IN; k += 256) {
        float v = bw[o * D_IN + k];
        __nv_bfloat16 h = __float2bfloat16(v);
        g_Wh[rb + k] = h;
        g_Wl[rb + k] = __float2bfloat16(v - __bfloat162float(h));
    }
    const float* sp = sw + (size_t)o * (D_IN * NB);
    for (int k = t; k < D_IN * NB; k += 256) {
        float v = sp[k];
        __nv_bfloat16 h = __float2bfloat16(v);
        g_Wh[rb + D_IN + k] = h;
        g_Wl[rb + D_IN + k] = __float2bfloat16(v - __bfloat162float(h));
    }
}

// ---------------------------------------------------------------------------
// Kernel 1: layernorm + features, written as bf16 hi/lo split
// ---------------------------------------------------------------------------
__global__ void feat_kernel(const float* __restrict__ x,
                            const float* __restrict__ gamma,
                            const float* __restrict__ beta) {
    const int row = blockIdx.x;
    const int t   = threadIdx.x;        // 256 threads, 2 dims each
    const float* xr = x + (size_t)row * D_IN;

    float v0 = xr[t];
    float v1 = xr[t + 256];
    float s  = v0 + v1;
    float s2 = v0 * v0 + v1 * v1;
    #pragma unroll
    for (int off = 16; off; off >>= 1) {
        s  += __shfl_xor_sync(0xFFFFFFFFu, s,  off);
        s2 += __shfl_xor_sync(0xFFFFFFFFu, s2, off);
    }
    __shared__ float red[16];
    __shared__ float mu_s, rstd_s;
    int wid = t >> 5, lane = t & 31;
    if (lane == 0) { red[wid] = s; red[8 + wid] = s2; }
    __syncthreads();
    if (t == 0) {
        float ts = 0.f, ts2 = 0.f;
        #pragma unroll
        for (int i = 0; i < 8; i++) { ts += red[i]; ts2 += red[8 + i]; }
        float mu  = ts * (1.0f / 512.0f);
        float var = ts2 * (1.0f / 512.0f) - mu * mu;
        mu_s   = mu;
        rstd_s = rsqrtf(var + 1e-5f);
    }
    __syncthreads();
    const float mu = mu_s, rstd = rstd_s;

    size_t rb = (size_t)row * KTOT;
    const float H    = 3.0f / 5.0f;
    const float INVD = 7.0f / 3.0f;

    #pragma unroll
    for (int half = 0; half < 2; half++) {
        const int   d  = t + half * 256;
        const float xv = half ? v1 : v0;
        const float xn = (xv - mu) * rstd * gamma[d] + beta[d];

        float rl = fmaxf(xn, 0.0f);
        __nv_bfloat16 rh = __float2bfloat16(rl);
        g_Fh[rb + d] = rh;
        g_Fl[rb + d] = __float2bfloat16(rl - __bfloat162float(rh));

        // Cox-de Boor, uniform knots t_i = (i-3)*H - 1.5, i=0..11
        float b[11];
        #pragma unroll
        for (int i = 0; i < 11; i++) {
            float t0 = (float)(i - 3) * H - 1.5f;
            float t1 = (float)(i - 2) * H - 1.5f;
            b[i] = (xn >= t0 && xn < t1) ? 1.0f : 0.0f;
        }
        #pragma unroll
        for (int k = 1; k <= 3; k++) {
            const float inv = 1.0f / ((float)k * H);
            #pragma unroll
            for (int i = 0; i + k < 11; i++) {
                float ti   = (float)(i - 3) * H - 1.5f;
                float tik1 = (float)(i + k - 2) * H - 1.5f;
                float left  = (xn - ti) * inv;
                float right = (tik1 - xn) * inv;
                b[i] = left * b[i] + right * b[i + 1];
            }
        }

        __nv_bfloat16 oh[8], ol[8];
        #pragma unroll
        for (int j = 0; j < 8; j++) {
            float g = -1.5f + (float)j * (3.0f / 7.0f);
            float u = (xn - g) * INVD;
            float f = b[j] + __expf(-u * u);
            __nv_bfloat16 h = __float2bfloat16(f);
            oh[j] = h;
            ol[j] = __float2bfloat16(f - __bfloat162float(h));
        }
        *(uint4*)(&g_Fh[rb + D_IN + (size_t)d * NB]) = *(const uint4*)oh;
        *(uint4*)(&g_Fl[rb + D_IN + (size_t)d * NB]) = *(const uint4*)ol;
    }
}

// ---------------------------------------------------------------------------
// Kernel 2: mma.sync bf16 GEMM with hi/lo compensation
//   C = Fh*Wh^T + Fh*Wl^T + Fl*Wh^T   (fp32 accumulators)
// CTA: 128(M) x 128(N), 8 warps (4m x 2n), warp tile 32x64.
// 2-stage cp.async pipeline, 2 CTAs/SM.
// ---------------------------------------------------------------------------
__global__ __launch_bounds__(256, 2) void gemm_kernel(float* __restrict__ C) {
    extern __shared__ char smem[];
    const uint32_t sbase = smem_u32(smem);
    const int t    = threadIdx.x;
    const int wid  = t >> 5;
    const int wm   = wid & 3;           // m sub-tile (0..3), 32 rows each
    const int wn   = wid >> 2;          // n sub-tile (0..1), 64 cols each
    const int lane = t & 31;
    const int m0   = blockIdx.y * BM;
    const int n0   = blockIdx.x * BN;

    const __nv_bfloat16* Ah_g = g_Fh + (size_t)m0 * KTOT;
    const __nv_bfloat16* Al_g = g_Fl + (size_t)m0 * KTOT;
    const __nv_bfloat16* Bh_g = g_Wh + (size_t)n0 * KTOT;
    const __nv_bfloat16* Bl_g = g_Wl + (size_t)n0 * KTOT;

    // Per-lane ldmatrix base offsets
    //   A (x4 over m16 x k16): row=(l>>3 &1)*8 + (l&7), kchunk=(l>>4)*16B
    const uint32_t a_off = (uint32_t)((((lane >> 3) & 1) * 8 + (lane & 7)) * ASTRIDE
                                      + (lane >> 4) * 16);
    //   B (x4 over two n8 blocks x k16): nrow=(l>>4 &1)*8 + (l&7), kchunk=(l>>3 &1)*16B
    const uint32_t b_off = (uint32_t)((((lane >> 4) & 1) * 8 + (lane & 7)) * ASTRIDE
                                      + ((lane >> 3) & 1) * 16);

    float acc[2][8][4];
    #pragma unroll
    for (int i = 0; i < 2; i++)
        #pragma unroll
        for (int j = 0; j < 8; j++)
            #pragma unroll
            for (int q = 0; q < 4; q++) acc[i][j][q] = 0.0f;

    // ---- stage loader: 8 cp.async of 16B per thread (256 threads) ----
    // A tile: 128 rows x 4 chunks = 512 units x2 mats; B same.
    auto load_stage = [&](int st, int kc) {
        const uint32_t stage = sbase + st * STG_BYTES;
        #pragma unroll
        for (int r = 0; r < 2; r++) {
            int u = t + r * 256;               // 0..511
            int row = u >> 2, ch = u & 3;
            size_t go = (size_t)row * KTOT + kc + ch * 8;
            uint32_t so = (uint32_t)(row * ASTRIDE + ch * 16);
            cp_async16(stage + so,            Ah_g + go);
            cp_async16(stage + A_BYTES + so,  Al_g + go);
        }
        #pragma unroll
        for (int r = 0; r < 2; r++) {
            int u = t + r * 256;               // 0..511
            int row = u >> 2, ch = u & 3;
            size_t go = (size_t)row * KTOT + kc + ch * 8;
            uint32_t so = (uint32_t)(row * ASTRIDE + ch * 16);
            cp_async16(stage + 2 * A_BYTES + so,            Bh_g + go);
            cp_async16(stage + 2 * A_BYTES + B_BYTES + so,  Bl_g + go);
        }
    };

    load_stage(0, 0);
    CP_COMMIT();

    for (int i = 0; i < NITER; i++) {
        if (i + 1 < NITER) {
            load_stage((i + 1) & 1, (i + 1) * BK);
            CP_COMMIT();
            CP_WAIT(1);
        } else {
            CP_WAIT(0);
        }
        __syncthreads();

        const uint32_t stage = sbase + (i & 1) * STG_BYTES;
        const uint32_t sAh = stage;
        const uint32_t sAl = stage + A_BYTES;
        const uint32_t sBh = stage + 2 * A_BYTES;
        const uint32_t sBl = stage + 2 * A_BYTES + B_BYTES;
        const uint32_t awarp = (uint32_t)(wm * 32 * ASTRIDE);
        const uint32_t bwarp = (uint32_t)(wn * 64 * ASTRIDE);

        #pragma unroll
        for (int s = 0; s < 2; s++) {       // two k16 steps
            const uint32_t ks = (uint32_t)(s * 32);   // 16 bf16 = 32 bytes
            uint32_t ah[2][4], al[2][4];
            #pragma unroll
            for (int im = 0; im < 2; im++) {
                ldsm4(ah[im], sAh + awarp + (uint32_t)(im * 16 * ASTRIDE) + a_off + ks);
                ldsm4(al[im], sAl + awarp + (uint32_t)(im * 16 * ASTRIDE) + a_off + ks);
            }
            // B fragments loaded per 16-col group to bound register pressure
            #pragma unroll
            for (int jj = 0; jj < 4; jj++) {
                uint32_t bh[4], bl[4];
                ldsm4(bh, sBh + bwarp + (uint32_t)(jj * 16 * ASTRIDE) + b_off + ks);
                ldsm4(bl, sBl + bwarp + (uint32_t)(jj * 16 * ASTRIDE) + b_off + ks);
                #pragma unroll
                for (int im = 0; im < 2; im++)
                    #pragma unroll
                    for (int jh = 0; jh < 2; jh++) {    // two n8 halves
                        int j = jj * 2 + jh;
                        uint32_t bh0 = bh[jh * 2], bh1 = bh[jh * 2 + 1];
                        uint32_t bl0 = bl[jh * 2], bl1 = bl[jh * 2 + 1];
                        mma16816(acc[im][j], ah[im], bh0, bh1);   // hi*hi
                        mma16816(acc[im][j], ah[im], bl0, bl1);   // hi*lo
                        mma16816(acc[im][j], al[im], bh0, bh1);   // lo*hi
                    }
            }
        }
        __syncthreads();   // all warps done with this stage before refill
    }

    // Writeout: row = m0 + wm*32 + im*16 + lane/4 (+8),
    //           col = n0 + wn*64 + j*8 + (lane%4)*2
    #pragma unroll
    for (int im = 0; im < 2; im++) {
        int r0 = m0 + wm * 32 + im * 16 + (lane >> 2);
        #pragma unroll
        for (int j = 0; j < 8; j++) {
            int cc = n0 + wn * 64 + j * 8 + (lane & 3) * 2;
            *(float2*)(C + (size_t)r0 * N_OUT + cc) =
                make_float2(acc[im][j][0], acc[im][j][1]);
            *(float2*)(C + (size_t)(r0 + 8) * N_OUT + cc) =
                make_float2(acc[im][j][2], acc[im][j][3]);
        }
    }
}

// ---------------------------------------------------------------------------
extern "C" void kernel_launch(void* const* d_in, const int* in_sizes, int n_in,
                              void* d_out, int out_size) {
    const float* x        = (const float*)d_in[0];
    const float* ln_gamma = (const float*)d_in[1];
    const float* ln_beta  = (const float*)d_in[2];
    const float* base_w   = (const float*)d_in[3];
    const float* spline_w = (const float*)d_in[4];
    (void)in_sizes; (void)n_in; (void)out_size;

    cudaFuncSetAttribute(gemm_kernel, cudaFuncAttributeMaxDynamicSharedMemorySize, SMEM_TOTAL);

    prep_kernel<<<N_OUT, 256>>>(base_w, spline_w);
    feat_kernel<<<M_ROWS, 256>>>(x, ln_gamma, ln_beta);
    dim3 grid(N_OUT / BN, M_ROWS / BM);   // (4, 128)
    gemm_kernel<<<grid, 256, SMEM_TOTAL>>>((float*)d_out);
}